// round 11
// baseline (speedup 1.0000x reference)
#include <cuda_runtime.h>
#include <math.h>
#include <math_constants.h>

#define B_   32
#define V_   2048
#define K_   40
#define KP1  41
#define FIN  64
#define D_   4
#define P_   64
#define FILT 128
#define N_   (B_ * V_)
#define QPB  8
#define FULL 0xffffffffu

// ---- scratch (static device arrays: no allocation allowed) ----
__device__ float g_coords[N_ * 4];                  // 1 MB
__device__ float g_feats[(size_t)N_ * FIN];         // 16 MB
__device__ float g_coll[(size_t)N_ * 2 * P_];       // 32 MB

// ============================================================
// Kernel 1: coords = x@W_s + b_s ; feats = x@W_f + b_f
// ============================================================
__global__ void __launch_bounds__(256) k_transform(
    const float* __restrict__ x,
    const float* __restrict__ Ws, const float* __restrict__ bs,
    const float* __restrict__ Wf, const float* __restrict__ bf)
{
    __shared__ float xsT[64 * 65];
    __shared__ float wfs[64 * 64];
    __shared__ float wss[64 * 4];

    const int tid = threadIdx.x;
    const int r0 = blockIdx.x * 64;

    #pragma unroll
    for (int i = 0; i < 4; i++) {
        int f = tid + i * 256;
        reinterpret_cast<float4*>(wfs)[f] =
            reinterpret_cast<const float4*>(Wf)[f];
    }
    wss[tid] = Ws[tid];

    #pragma unroll
    for (int i = 0; i < 4; i++) {
        int f   = tid + i * 256;
        int row = f >> 4;
        int kq  = (f & 15) * 4;
        float4 v = *reinterpret_cast<const float4*>(
            x + (size_t)(r0 + row) * FIN + kq);
        xsT[(kq + 0) * 65 + row] = v.x;
        xsT[(kq + 1) * 65 + row] = v.y;
        xsT[(kq + 2) * 65 + row] = v.z;
        xsT[(kq + 3) * 65 + row] = v.w;
    }
    __syncthreads();

    const int tx = tid & 15, ty = tid >> 4;
    float acc[4][4];
    #pragma unroll
    for (int i = 0; i < 4; i++)
        #pragma unroll
        for (int j = 0; j < 4; j++) acc[i][j] = 0.f;

    #pragma unroll 16
    for (int k = 0; k < 64; k++) {
        float a0 = xsT[k * 65 + ty * 4 + 0];
        float a1 = xsT[k * 65 + ty * 4 + 1];
        float a2 = xsT[k * 65 + ty * 4 + 2];
        float a3 = xsT[k * 65 + ty * 4 + 3];
        float4 b = *reinterpret_cast<const float4*>(&wfs[k * 64 + tx * 4]);
        acc[0][0] = fmaf(a0, b.x, acc[0][0]); acc[0][1] = fmaf(a0, b.y, acc[0][1]);
        acc[0][2] = fmaf(a0, b.z, acc[0][2]); acc[0][3] = fmaf(a0, b.w, acc[0][3]);
        acc[1][0] = fmaf(a1, b.x, acc[1][0]); acc[1][1] = fmaf(a1, b.y, acc[1][1]);
        acc[1][2] = fmaf(a1, b.z, acc[1][2]); acc[1][3] = fmaf(a1, b.w, acc[1][3]);
        acc[2][0] = fmaf(a2, b.x, acc[2][0]); acc[2][1] = fmaf(a2, b.y, acc[2][1]);
        acc[2][2] = fmaf(a2, b.z, acc[2][2]); acc[2][3] = fmaf(a2, b.w, acc[2][3]);
        acc[3][0] = fmaf(a3, b.x, acc[3][0]); acc[3][1] = fmaf(a3, b.y, acc[3][1]);
        acc[3][2] = fmaf(a3, b.z, acc[3][2]); acc[3][3] = fmaf(a3, b.w, acc[3][3]);
    }

    float4 bfv = *reinterpret_cast<const float4*>(bf + tx * 4);
    #pragma unroll
    for (int i = 0; i < 4; i++) {
        int row = r0 + ty * 4 + i;
        float4 o;
        o.x = acc[i][0] + bfv.x; o.y = acc[i][1] + bfv.y;
        o.z = acc[i][2] + bfv.z; o.w = acc[i][3] + bfv.w;
        *reinterpret_cast<float4*>(g_feats + (size_t)row * FIN + tx * 4) = o;
    }

    {
        int crow = tid >> 2, cc = tid & 3;
        float a2 = 0.f;
        #pragma unroll 16
        for (int k = 0; k < 64; k++)
            a2 = fmaf(xsT[k * 65 + crow], wss[k * 4 + cc], a2);
        g_coords[(r0 + crow) * 4 + cc] = a2 + bs[cc];
    }
}

// ============================================================
// warp bitonic sort of 64 u32 (2 regs/lane, element e = r*32+lane)
// ============================================================
__device__ __forceinline__ void bstep_u32(unsigned &v, int ebase, int sz, int st, int lane) {
    unsigned o = __shfl_xor_sync(FULL, v, st);
    bool up    = ((ebase & sz) == 0);
    bool lower = ((lane & st) == 0);
    unsigned mn = min(v, o), mx = max(v, o);
    v = (lower == up) ? mn : mx;
}

__device__ __forceinline__ void sort64_u32(unsigned &s0, unsigned &s1, int lane) {
    #pragma unroll
    for (int sz = 2; sz <= 32; sz <<= 1) {
        #pragma unroll
        for (int st = sz >> 1; st >= 1; st >>= 1) {
            bstep_u32(s0, lane, sz, st, lane);
            bstep_u32(s1, 32 + lane, sz, st, lane);
        }
    }
    { unsigned mn = min(s0, s1), mx = max(s0, s1); s0 = mn; s1 = mx; }
    #pragma unroll
    for (int st = 16; st >= 1; st >>= 1) {
        bstep_u32(s0, lane, 64, st, lane);
        bstep_u32(s1, 32 + lane, 64, st, lane);
    }
}

// ============================================================
// Kernel 2: exact KNN + Gaussian-weighted max/mean pooling.
// ============================================================
__device__ __forceinline__ unsigned keyof(float d2) {
    unsigned u = __float_as_uint(d2);
    u ^= (u & 0x80000000u) ? 0xFFFFFFFFu : 0x80000000u;
    return u;
}
__device__ __forceinline__ unsigned long long ullmin_(unsigned long long a, unsigned long long b) {
    return a < b ? a : b;
}

__global__ void __launch_bounds__(256, 3) k_knn()
{
    __shared__ float4 sc[V_];                      // 32 KB
    __shared__ float  ssq[V_];                     // 8 KB
    __shared__ unsigned candk[QPB][64];            // 2 KB (candidate keys)
    __shared__ float2 s_iw[QPB][K_];               // 2.5 KB (weight, feat offset)

    const int b   = blockIdx.y;
    const int tid = threadIdx.x;
    const float4* cg = reinterpret_cast<const float4*>(g_coords) + (size_t)b * V_;
    for (int t = tid; t < V_; t += 256) {
        float4 c = cg[t];
        sc[t]  = c;
        float s = c.x * c.x;
        s = fmaf(c.y, c.y, s); s = fmaf(c.z, c.z, s); s = fmaf(c.w, c.w, s);
        ssq[t] = s;
    }
    __syncthreads();

    const int w    = tid >> 5;
    const int lane = tid & 31;
    const int q    = blockIdx.x * QPB + w;
    const unsigned lanemask_lt = (1u << lane) - 1u;

    const float4 qc  = sc[q];
    const float  qsq = ssq[q];

    // ---- distance keys + fused per-lane two smallest ----
    unsigned key[64];
    unsigned m1 = 0xFFFFFFFFu, m2 = 0xFFFFFFFFu;
    #pragma unroll
    for (int j = 0; j < 64; j++) {
        int idx = j * 32 + lane;
        float4 c = sc[idx];
        float dot = qc.x * c.x;
        dot = fmaf(qc.y, c.y, dot);
        dot = fmaf(qc.z, c.z, dot);
        dot = fmaf(qc.w, c.w, dot);
        float d2 = qsq + ssq[idx] - 2.f * dot;
        unsigned u = keyof(d2);
        key[j] = u;
        unsigned nm1 = min(m1, u);
        unsigned nm2 = min(m2, max(m1, u));
        m1 = nm1; m2 = nm2;
    }

    // ---- B = 41st smallest of min2 union (upper bound on threshold) ----
    unsigned s0 = m1, s1 = m2;
    sort64_u32(s0, s1, lane);
    const unsigned B    = __shfl_sync(FULL, s1, 8);   // element 40
    const unsigned gmin = __shfl_sync(FULL, s0, 0);   // element 0

    // ---- candidate membership mask (key <= B), prefix-scan compaction ----
    unsigned long long candmask = 0ull;
    #pragma unroll
    for (int j = 0; j < 64; j++)
        if (key[j] <= B) candmask |= (1ull << j);

    int myCnt = __popcll(candmask);
    int scan = myCnt;
    #pragma unroll
    for (int o = 1; o < 32; o <<= 1) {
        int v = __shfl_up_sync(FULL, scan, o);
        if (lane >= o) scan += v;
    }
    const int nc   = __shfl_sync(FULL, scan, 31);
    int pos = scan - myCnt;

    unsigned long long selmask = 0ull;   // final selected set (41 incl drop)

    if (nc <= 64) {
        // ======== FAST PATH ========
        {
            unsigned long long m = candmask;
            while (m) {
                int j = __ffsll((long long)m) - 1;
                m &= m - 1;
                candk[w][pos++] = key[j];
            }
        }
        __syncwarp();
        unsigned c0 = (lane      < nc) ? candk[w][lane]      : 0xFFFFFFFFu;
        unsigned c1 = (32 + lane < nc) ? candk[w][32 + lane] : 0xFFFFFFFFu;
        sort64_u32(c0, c1, lane);
        const unsigned T  = __shfl_sync(FULL, c1, 8);    // element 40 = 41st key
        const unsigned T1 = __shfl_sync(FULL, c1, 9);    // element 41
        const bool tie = (nc >= 42) && (T1 == T);

        if (!tie) {
            #pragma unroll
            for (int j = 0; j < 64; j++)
                if (key[j] <= T) selmask |= (1ull << j);
        } else {
            int c_less = 0;
            #pragma unroll
            for (int j = 0; j < 64; j++) c_less += (key[j] < T) ? 1 : 0;
            c_less = __reduce_add_sync(FULL, c_less);
            const int take_eq = KP1 - c_less;
            int running = 0;
            #pragma unroll
            for (int j = 0; j < 64; j++) {
                bool eq = (key[j] == T);
                unsigned bal = __ballot_sync(FULL, eq);
                bool sel = (key[j] < T);
                if (eq) {
                    int rank = running + __popc(bal & lanemask_lt);
                    sel = sel || (rank < take_eq);
                }
                running += __popc(bal);
                if (sel) selmask |= (1ull << j);
            }
        }
    } else {
        // ======== FALLBACK (degenerate): exact binary search ========
        unsigned lo = gmin, hi = B;
        unsigned T = 0;
        int cT = 0;
        bool exact = false;
        while (lo < hi) {
            unsigned mid = lo + ((hi - lo) >> 1);
            int c = 0;
            #pragma unroll
            for (int j = 0; j < 64; j++) c += (key[j] <= mid) ? 1 : 0;
            c = __reduce_add_sync(FULL, c);
            if (c == KP1) {
                unsigned mx = 0;
                #pragma unroll
                for (int j = 0; j < 64; j++) if (key[j] <= mid) mx = max(mx, key[j]);
                T = __reduce_max_sync(FULL, mx);
                cT = KP1; exact = true; break;
            }
            if (c > KP1) hi = mid; else lo = mid + 1;
        }
        if (!exact) {
            T = lo;
            int c = 0;
            #pragma unroll
            for (int j = 0; j < 64; j++) c += (key[j] <= T) ? 1 : 0;
            cT = __reduce_add_sync(FULL, c);
        }
        if (cT == KP1) {
            #pragma unroll
            for (int j = 0; j < 64; j++)
                if (key[j] <= T) selmask |= (1ull << j);
        } else {
            int c_less = 0;
            #pragma unroll
            for (int j = 0; j < 64; j++) c_less += (key[j] < T) ? 1 : 0;
            c_less = __reduce_add_sync(FULL, c_less);
            const int take_eq = KP1 - c_less;
            int running = 0;
            #pragma unroll
            for (int j = 0; j < 64; j++) {
                bool eq = (key[j] == T);
                unsigned bal = __ballot_sync(FULL, eq);
                bool sel = (key[j] < T);
                if (eq) {
                    int rank = running + __popc(bal & lanemask_lt);
                    sel = sel || (rank < take_eq);
                }
                running += __popc(bal);
                if (sel) selmask |= (1ull << j);
            }
        }
    }

    // ---- common epilogue: drop = min composite; write (weight, offset) ----
    unsigned long long mymin = 0xFFFFFFFFFFFFFFFFull;
    {
        unsigned long long m = selmask;
        while (m) {
            int j = __ffsll((long long)m) - 1;
            m &= m - 1;
            unsigned long long ck =
                ((unsigned long long)key[j] << 32) | (unsigned)(j * 32 + lane);
            mymin = ullmin_(mymin, ck);
        }
    }
    #pragma unroll
    for (int o = 16; o; o >>= 1)
        mymin = ullmin_(mymin, __shfl_xor_sync(FULL, mymin, o));
    const int dropidx = (int)(unsigned)(mymin & 0xffffffffull);
    if ((dropidx & 31) == lane)
        selmask &= ~(1ull << (dropidx >> 5));

    {
        int cnt = __popcll(selmask);
        int sc2 = cnt;
        #pragma unroll
        for (int o = 1; o < 32; o <<= 1) {
            int v = __shfl_up_sync(FULL, sc2, o);
            if (lane >= o) sc2 += v;
        }
        int p = sc2 - cnt;
        unsigned long long m = selmask;
        while (m) {
            int j = __ffsll((long long)m) - 1;
            m &= m - 1;
            int idx = j * 32 + lane;
            float4 c = sc[idx];
            float dx = qc.x - c.x, dy = qc.y - c.y, dz = qc.z - c.z, dw = qc.w - c.w;
            float dist = dx * dx;
            dist = fmaf(dy, dy, dist);
            dist = fmaf(dz, dz, dist);
            dist = fmaf(dw, dw, dist);
            float2 iw;
            iw.x = expf(-fabsf(dist * 10.f));
            iw.y = __int_as_float(idx << 6);   // element offset idx*64
            if (p < K_) s_iw[w][p] = iw;
            p++;
        }
    }
    __syncwarp();

    // ---- weighted max / mean pooling: lane owns features 2l, 2l+1 ----
    const float* fb = g_feats + (size_t)b * V_ * FIN + 2 * lane;
    float mx0 = -CUDART_INF_F, mx1 = -CUDART_INF_F, sm0 = 0.f, sm1 = 0.f;
    #pragma unroll 8
    for (int n = 0; n < K_; n++) {
        float2 iw = s_iw[w][n];
        int off = __float_as_int(iw.y);
        float2 f = *reinterpret_cast<const float2*>(fb + off);
        float v0 = f.x * iw.x, v1 = f.y * iw.x;
        mx0 = fmaxf(mx0, v0); mx1 = fmaxf(mx1, v1);
        sm0 += v0;            sm1 += v1;
    }
    const int grow = b * V_ + q;
    float* o = g_coll + (size_t)grow * (2 * P_);
    float2 omx; omx.x = mx0; omx.y = mx1;
    float2 osm; osm.x = sm0 * (1.f / (float)K_); osm.y = sm1 * (1.f / (float)K_);
    *reinterpret_cast<float2*>(o + 2 * lane)      = omx;
    *reinterpret_cast<float2*>(o + 64 + 2 * lane) = osm;
}

// ============================================================
// Kernel 3: out = tanh([x | collected] @ W_out + b_out)
// 128x128 tile, 8x8/thread, BK=16, double-buffered smem
// ============================================================
__device__ __forceinline__ const float* a_src_ptr(const float* __restrict__ x,
                                                  int row, int gk) {
    return (gk < FIN) ? (x + (size_t)row * FIN + gk)
                      : (g_coll + (size_t)row * 128 + (gk - FIN));
}

__global__ void __launch_bounds__(256, 2) k_out(
    const float* __restrict__ x,
    const float* __restrict__ Wout, const float* __restrict__ bout,
    float* __restrict__ out)
{
    __shared__ float As[2][16 * 132];
    __shared__ float Bs[2][16 * 128];

    const int tidx = threadIdx.x;
    const int tx = tidx & 15, ty = tidx >> 4;
    const int r0 = blockIdx.x * 128;

    const int rowA0 = tidx >> 2,          kqA0 = (tidx & 3) * 4;
    const int rowA1 = (tidx + 256) >> 2,  kqA1 = ((tidx + 256) & 3) * 4;
    const int krB0  = tidx >> 5,          nB0  = (tidx & 31) * 4;
    const int krB1  = (tidx + 256) >> 5,  nB1  = ((tidx + 256) & 31) * 4;

    float acc[8][8];
    #pragma unroll
    for (int i = 0; i < 8; i++)
        #pragma unroll
        for (int j = 0; j < 8; j++) acc[i][j] = 0.f;

    // prologue: load tile 0 into regs, store to buf 0
    float4 va0 = *reinterpret_cast<const float4*>(a_src_ptr(x, r0 + rowA0, kqA0));
    float4 va1 = *reinterpret_cast<const float4*>(a_src_ptr(x, r0 + rowA1, kqA1));
    float4 vb0 = *reinterpret_cast<const float4*>(Wout + (size_t)krB0 * 128 + nB0);
    float4 vb1 = *reinterpret_cast<const float4*>(Wout + (size_t)krB1 * 128 + nB1);
    {
        As[0][(kqA0 + 0) * 132 + rowA0] = va0.x;
        As[0][(kqA0 + 1) * 132 + rowA0] = va0.y;
        As[0][(kqA0 + 2) * 132 + rowA0] = va0.z;
        As[0][(kqA0 + 3) * 132 + rowA0] = va0.w;
        As[0][(kqA1 + 0) * 132 + rowA1] = va1.x;
        As[0][(kqA1 + 1) * 132 + rowA1] = va1.y;
        As[0][(kqA1 + 2) * 132 + rowA1] = va1.z;
        As[0][(kqA1 + 3) * 132 + rowA1] = va1.w;
        *reinterpret_cast<float4*>(&Bs[0][krB0 * 128 + nB0]) = vb0;
        *reinterpret_cast<float4*>(&Bs[0][krB1 * 128 + nB1]) = vb1;
    }
    __syncthreads();

    #pragma unroll
    for (int kt = 0; kt < 12; kt++) {
        const int cur = kt & 1;
        if (kt < 11) {
            int g0 = (kt + 1) * 16;
            va0 = *reinterpret_cast<const float4*>(a_src_ptr(x, r0 + rowA0, g0 + kqA0));
            va1 = *reinterpret_cast<const float4*>(a_src_ptr(x, r0 + rowA1, g0 + kqA1));
            vb0 = *reinterpret_cast<const float4*>(Wout + (size_t)(g0 + krB0) * 128 + nB0);
            vb1 = *reinterpret_cast<const float4*>(Wout + (size_t)(g0 + krB1) * 128 + nB1);
        }

        const float* Ac = As[cur];
        const float* Bc = Bs[cur];
        #pragma unroll
        for (int k = 0; k < 16; k++) {
            float a[8], bb[8];
            *reinterpret_cast<float4*>(&a[0]) =
                *reinterpret_cast<const float4*>(&Ac[k * 132 + ty * 8]);
            *reinterpret_cast<float4*>(&a[4]) =
                *reinterpret_cast<const float4*>(&Ac[k * 132 + ty * 8 + 4]);
            *reinterpret_cast<float4*>(&bb[0]) =
                *reinterpret_cast<const float4*>(&Bc[k * 128 + tx * 8]);
            *reinterpret_cast<float4*>(&bb[4]) =
                *reinterpret_cast<const float4*>(&Bc[k * 128 + tx * 8 + 4]);
            #pragma unroll
            for (int i = 0; i < 8; i++)
                #pragma unroll
                for (int j = 0; j < 8; j++)
                    acc[i][j] = fmaf(a[i], bb[j], acc[i][j]);
        }

        if (kt < 11) {
            const int nxt = cur ^ 1;
            As[nxt][(kqA0 + 0) * 132 + rowA0] = va0.x;
            As[nxt][(kqA0 + 1) * 132 + rowA0] = va0.y;
            As[nxt][(kqA0 + 2) * 132 + rowA0] = va0.z;
            As[nxt][(kqA0 + 3) * 132 + rowA0] = va0.w;
            As[nxt][(kqA1 + 0) * 132 + rowA1] = va1.x;
            As[nxt][(kqA1 + 1) * 132 + rowA1] = va1.y;
            As[nxt][(kqA1 + 2) * 132 + rowA1] = va1.z;
            As[nxt][(kqA1 + 3) * 132 + rowA1] = va1.w;
            *reinterpret_cast<float4*>(&Bs[nxt][krB0 * 128 + nB0]) = vb0;
            *reinterpret_cast<float4*>(&Bs[nxt][krB1 * 128 + nB1]) = vb1;
            __syncthreads();
        }
    }

    float bias[8];
    *reinterpret_cast<float4*>(&bias[0]) = *reinterpret_cast<const float4*>(&bout[tx * 8]);
    *reinterpret_cast<float4*>(&bias[4]) = *reinterpret_cast<const float4*>(&bout[tx * 8 + 4]);

    #pragma unroll
    for (int i = 0; i < 8; i++) {
        int row = r0 + ty * 8 + i;
        float4 o0, o1;
        o0.x = tanhf(acc[i][0] + bias[0]);
        o0.y = tanhf(acc[i][1] + bias[1]);
        o0.z = tanhf(acc[i][2] + bias[2]);
        o0.w = tanhf(acc[i][3] + bias[3]);
        o1.x = tanhf(acc[i][4] + bias[4]);
        o1.y = tanhf(acc[i][5] + bias[5]);
        o1.z = tanhf(acc[i][6] + bias[6]);
        o1.w = tanhf(acc[i][7] + bias[7]);
        *reinterpret_cast<float4*>(&out[(size_t)row * 128 + tx * 8])     = o0;
        *reinterpret_cast<float4*>(&out[(size_t)row * 128 + tx * 8 + 4]) = o1;
    }
}

// ============================================================
extern "C" void kernel_launch(void* const* d_in, const int* in_sizes, int n_in,
                              void* d_out, int out_size)
{
    const float* x    = (const float*)d_in[0];
    const float* Ws   = (const float*)d_in[2];
    const float* bs   = (const float*)d_in[3];
    const float* Wf   = (const float*)d_in[4];
    const float* bf   = (const float*)d_in[5];
    const float* Wout = (const float*)d_in[6];
    const float* bout = (const float*)d_in[7];
    float* out = (float*)d_out;

    k_transform<<<N_ / 64, 256>>>(x, Ws, bs, Wf, bf);
    k_knn<<<dim3(V_ / QPB, B_), 256>>>();
    k_out<<<N_ / 128, 256>>>(x, Wout, bout, out);
}

// round 12
// speedup vs baseline: 1.0144x; 1.0144x over previous
#include <cuda_runtime.h>
#include <math.h>
#include <math_constants.h>

#define B_   32
#define V_   2048
#define K_   40
#define KP1  41
#define FIN  64
#define D_   4
#define P_   64
#define FILT 128
#define N_   (B_ * V_)
#define QPB  8
#define FULL 0xffffffffu

// ---- scratch (static device arrays: no allocation allowed) ----
__device__ float g_coords[N_ * 4];                  // 1 MB
__device__ float g_feats[(size_t)N_ * FIN];         // 16 MB
__device__ float g_coll[(size_t)N_ * 2 * P_];       // 32 MB

// ============================================================
// Kernel 1: coords = x@W_s + b_s ; feats = x@W_f + b_f
// ============================================================
__global__ void __launch_bounds__(256) k_transform(
    const float* __restrict__ x,
    const float* __restrict__ Ws, const float* __restrict__ bs,
    const float* __restrict__ Wf, const float* __restrict__ bf)
{
    __shared__ float xsT[64 * 65];
    __shared__ float wfs[64 * 64];
    __shared__ float wss[64 * 4];

    const int tid = threadIdx.x;
    const int r0 = blockIdx.x * 64;

    #pragma unroll
    for (int i = 0; i < 4; i++) {
        int f = tid + i * 256;
        reinterpret_cast<float4*>(wfs)[f] =
            reinterpret_cast<const float4*>(Wf)[f];
    }
    wss[tid] = Ws[tid];

    #pragma unroll
    for (int i = 0; i < 4; i++) {
        int f   = tid + i * 256;
        int row = f >> 4;
        int kq  = (f & 15) * 4;
        float4 v = *reinterpret_cast<const float4*>(
            x + (size_t)(r0 + row) * FIN + kq);
        xsT[(kq + 0) * 65 + row] = v.x;
        xsT[(kq + 1) * 65 + row] = v.y;
        xsT[(kq + 2) * 65 + row] = v.z;
        xsT[(kq + 3) * 65 + row] = v.w;
    }
    __syncthreads();

    const int tx = tid & 15, ty = tid >> 4;
    float acc[4][4];
    #pragma unroll
    for (int i = 0; i < 4; i++)
        #pragma unroll
        for (int j = 0; j < 4; j++) acc[i][j] = 0.f;

    #pragma unroll 16
    for (int k = 0; k < 64; k++) {
        float a0 = xsT[k * 65 + ty * 4 + 0];
        float a1 = xsT[k * 65 + ty * 4 + 1];
        float a2 = xsT[k * 65 + ty * 4 + 2];
        float a3 = xsT[k * 65 + ty * 4 + 3];
        float4 b = *reinterpret_cast<const float4*>(&wfs[k * 64 + tx * 4]);
        acc[0][0] = fmaf(a0, b.x, acc[0][0]); acc[0][1] = fmaf(a0, b.y, acc[0][1]);
        acc[0][2] = fmaf(a0, b.z, acc[0][2]); acc[0][3] = fmaf(a0, b.w, acc[0][3]);
        acc[1][0] = fmaf(a1, b.x, acc[1][0]); acc[1][1] = fmaf(a1, b.y, acc[1][1]);
        acc[1][2] = fmaf(a1, b.z, acc[1][2]); acc[1][3] = fmaf(a1, b.w, acc[1][3]);
        acc[2][0] = fmaf(a2, b.x, acc[2][0]); acc[2][1] = fmaf(a2, b.y, acc[2][1]);
        acc[2][2] = fmaf(a2, b.z, acc[2][2]); acc[2][3] = fmaf(a2, b.w, acc[2][3]);
        acc[3][0] = fmaf(a3, b.x, acc[3][0]); acc[3][1] = fmaf(a3, b.y, acc[3][1]);
        acc[3][2] = fmaf(a3, b.z, acc[3][2]); acc[3][3] = fmaf(a3, b.w, acc[3][3]);
    }

    float4 bfv = *reinterpret_cast<const float4*>(bf + tx * 4);
    #pragma unroll
    for (int i = 0; i < 4; i++) {
        int row = r0 + ty * 4 + i;
        float4 o;
        o.x = acc[i][0] + bfv.x; o.y = acc[i][1] + bfv.y;
        o.z = acc[i][2] + bfv.z; o.w = acc[i][3] + bfv.w;
        *reinterpret_cast<float4*>(g_feats + (size_t)row * FIN + tx * 4) = o;
    }

    {
        int crow = tid >> 2, cc = tid & 3;
        float a2 = 0.f;
        #pragma unroll 16
        for (int k = 0; k < 64; k++)
            a2 = fmaf(xsT[k * 65 + crow], wss[k * 4 + cc], a2);
        g_coords[(r0 + crow) * 4 + cc] = a2 + bs[cc];
    }
}

// ============================================================
// warp bitonic sort of 64 u32 (2 regs/lane, element e = r*32+lane)
// ============================================================
__device__ __forceinline__ void bstep_u32(unsigned &v, int ebase, int sz, int st, int lane) {
    unsigned o = __shfl_xor_sync(FULL, v, st);
    bool up    = ((ebase & sz) == 0);
    bool lower = ((lane & st) == 0);
    unsigned mn = min(v, o), mx = max(v, o);
    v = (lower == up) ? mn : mx;
}

__device__ __forceinline__ void sort64_u32(unsigned &s0, unsigned &s1, int lane) {
    #pragma unroll
    for (int sz = 2; sz <= 32; sz <<= 1) {
        #pragma unroll
        for (int st = sz >> 1; st >= 1; st >>= 1) {
            bstep_u32(s0, lane, sz, st, lane);
            bstep_u32(s1, 32 + lane, sz, st, lane);
        }
    }
    { unsigned mn = min(s0, s1), mx = max(s0, s1); s0 = mn; s1 = mx; }
    #pragma unroll
    for (int st = 16; st >= 1; st >>= 1) {
        bstep_u32(s0, lane, 64, st, lane);
        bstep_u32(s1, 32 + lane, 64, st, lane);
    }
}

// ============================================================
// Kernel 2: exact KNN + Gaussian-weighted max/mean pooling.
// ============================================================
__device__ __forceinline__ unsigned keyof(float d2) {
    unsigned u = __float_as_uint(d2);
    u ^= (u & 0x80000000u) ? 0xFFFFFFFFu : 0x80000000u;
    return u;
}
__device__ __forceinline__ unsigned long long ullmin_(unsigned long long a, unsigned long long b) {
    return a < b ? a : b;
}

// squared norm with the exact fmaf chain used everywhere
__device__ __forceinline__ float sqnorm(float4 c) {
    float s = c.x * c.x;
    s = fmaf(c.y, c.y, s); s = fmaf(c.z, c.z, s); s = fmaf(c.w, c.w, s);
    return s;
}

__global__ void __launch_bounds__(256, 2) k_knn()
{
    __shared__ float4 sc[V_];                      // 32 KB
    __shared__ unsigned candk[QPB][64];            // 2 KB (candidate keys)
    __shared__ float2 s_iw[QPB][K_];               // 2.5 KB (weight, feat offset)

    const int b   = blockIdx.y;
    const int tid = threadIdx.x;
    const float4* cg = reinterpret_cast<const float4*>(g_coords) + (size_t)b * V_;
    for (int t = tid; t < V_; t += 256)
        sc[t] = cg[t];
    __syncthreads();

    const int w    = tid >> 5;
    const int lane = tid & 31;
    const int q    = blockIdx.x * QPB + w;
    const unsigned lanemask_lt = (1u << lane) - 1u;

    const float4 qc  = sc[q];
    const float  qsq = sqnorm(qc);

    // ---- distance keys + fused per-lane two smallest ----
    // ssq recomputed in-loop with the identical fmaf chain (bit-exact).
    unsigned key[64];
    unsigned m1 = 0xFFFFFFFFu, m2 = 0xFFFFFFFFu;
    #pragma unroll
    for (int j = 0; j < 64; j++) {
        int idx = j * 32 + lane;
        float4 c = sc[idx];
        float dot = qc.x * c.x;
        dot = fmaf(qc.y, c.y, dot);
        dot = fmaf(qc.z, c.z, dot);
        dot = fmaf(qc.w, c.w, dot);
        float d2 = qsq + sqnorm(c) - 2.f * dot;
        unsigned u = keyof(d2);
        key[j] = u;
        unsigned nm1 = min(m1, u);
        unsigned nm2 = min(m2, max(m1, u));
        m1 = nm1; m2 = nm2;
    }

    // ---- B = 41st smallest of min2 union (upper bound on threshold) ----
    unsigned s0 = m1, s1 = m2;
    sort64_u32(s0, s1, lane);
    const unsigned B    = __shfl_sync(FULL, s1, 8);   // element 40
    const unsigned gmin = __shfl_sync(FULL, s0, 0);   // element 0

    // ---- candidate membership mask (key <= B), prefix-scan compaction ----
    unsigned long long candmask = 0ull;
    #pragma unroll
    for (int j = 0; j < 64; j++)
        if (key[j] <= B) candmask |= (1ull << j);

    int myCnt = __popcll(candmask);
    int scan = myCnt;
    #pragma unroll
    for (int o = 1; o < 32; o <<= 1) {
        int v = __shfl_up_sync(FULL, scan, o);
        if (lane >= o) scan += v;
    }
    const int nc   = __shfl_sync(FULL, scan, 31);
    int pos = scan - myCnt;

    unsigned long long selmask = 0ull;   // final selected set (41 incl drop)

    if (nc <= 64) {
        // ======== FAST PATH ========
        {
            unsigned long long m = candmask;
            while (m) {
                int j = __ffsll((long long)m) - 1;
                m &= m - 1;
                candk[w][pos++] = key[j];
            }
        }
        __syncwarp();
        unsigned c0 = (lane      < nc) ? candk[w][lane]      : 0xFFFFFFFFu;
        unsigned c1 = (32 + lane < nc) ? candk[w][32 + lane] : 0xFFFFFFFFu;
        sort64_u32(c0, c1, lane);
        const unsigned T  = __shfl_sync(FULL, c1, 8);    // element 40 = 41st key
        const unsigned T1 = __shfl_sync(FULL, c1, 9);    // element 41
        const bool tie = (nc >= 42) && (T1 == T);

        if (!tie) {
            #pragma unroll
            for (int j = 0; j < 64; j++)
                if (key[j] <= T) selmask |= (1ull << j);
        } else {
            int c_less = 0;
            #pragma unroll
            for (int j = 0; j < 64; j++) c_less += (key[j] < T) ? 1 : 0;
            c_less = __reduce_add_sync(FULL, c_less);
            const int take_eq = KP1 - c_less;
            int running = 0;
            #pragma unroll
            for (int j = 0; j < 64; j++) {
                bool eq = (key[j] == T);
                unsigned bal = __ballot_sync(FULL, eq);
                bool sel = (key[j] < T);
                if (eq) {
                    int rank = running + __popc(bal & lanemask_lt);
                    sel = sel || (rank < take_eq);
                }
                running += __popc(bal);
                if (sel) selmask |= (1ull << j);
            }
        }
    } else {
        // ======== FALLBACK (degenerate): exact binary search ========
        unsigned lo = gmin, hi = B;
        unsigned T = 0;
        int cT = 0;
        bool exact = false;
        while (lo < hi) {
            unsigned mid = lo + ((hi - lo) >> 1);
            int c = 0;
            #pragma unroll
            for (int j = 0; j < 64; j++) c += (key[j] <= mid) ? 1 : 0;
            c = __reduce_add_sync(FULL, c);
            if (c == KP1) {
                unsigned mx = 0;
                #pragma unroll
                for (int j = 0; j < 64; j++) if (key[j] <= mid) mx = max(mx, key[j]);
                T = __reduce_max_sync(FULL, mx);
                cT = KP1; exact = true; break;
            }
            if (c > KP1) hi = mid; else lo = mid + 1;
        }
        if (!exact) {
            T = lo;
            int c = 0;
            #pragma unroll
            for (int j = 0; j < 64; j++) c += (key[j] <= T) ? 1 : 0;
            cT = __reduce_add_sync(FULL, c);
        }
        if (cT == KP1) {
            #pragma unroll
            for (int j = 0; j < 64; j++)
                if (key[j] <= T) selmask |= (1ull << j);
        } else {
            int c_less = 0;
            #pragma unroll
            for (int j = 0; j < 64; j++) c_less += (key[j] < T) ? 1 : 0;
            c_less = __reduce_add_sync(FULL, c_less);
            const int take_eq = KP1 - c_less;
            int running = 0;
            #pragma unroll
            for (int j = 0; j < 64; j++) {
                bool eq = (key[j] == T);
                unsigned bal = __ballot_sync(FULL, eq);
                bool sel = (key[j] < T);
                if (eq) {
                    int rank = running + __popc(bal & lanemask_lt);
                    sel = sel || (rank < take_eq);
                }
                running += __popc(bal);
                if (sel) selmask |= (1ull << j);
            }
        }
    }

    // ---- common epilogue: drop = min composite; write (weight, offset) ----
    unsigned long long mymin = 0xFFFFFFFFFFFFFFFFull;
    {
        unsigned long long m = selmask;
        while (m) {
            int j = __ffsll((long long)m) - 1;
            m &= m - 1;
            unsigned long long ck =
                ((unsigned long long)key[j] << 32) | (unsigned)(j * 32 + lane);
            mymin = ullmin_(mymin, ck);
        }
    }
    #pragma unroll
    for (int o = 16; o; o >>= 1)
        mymin = ullmin_(mymin, __shfl_xor_sync(FULL, mymin, o));
    const int dropidx = (int)(unsigned)(mymin & 0xffffffffull);
    if ((dropidx & 31) == lane)
        selmask &= ~(1ull << (dropidx >> 5));

    {
        int cnt = __popcll(selmask);
        int sc2 = cnt;
        #pragma unroll
        for (int o = 1; o < 32; o <<= 1) {
            int v = __shfl_up_sync(FULL, sc2, o);
            if (lane >= o) sc2 += v;
        }
        int p = sc2 - cnt;
        unsigned long long m = selmask;
        while (m) {
            int j = __ffsll((long long)m) - 1;
            m &= m - 1;
            int idx = j * 32 + lane;
            float4 c = sc[idx];
            float dx = qc.x - c.x, dy = qc.y - c.y, dz = qc.z - c.z, dw = qc.w - c.w;
            float dist = dx * dx;
            dist = fmaf(dy, dy, dist);
            dist = fmaf(dz, dz, dist);
            dist = fmaf(dw, dw, dist);
            float2 iw;
            iw.x = expf(-fabsf(dist * 10.f));
            iw.y = __int_as_float(idx << 6);   // element offset idx*64
            if (p < K_) s_iw[w][p] = iw;
            p++;
        }
    }
    __syncwarp();

    // ---- weighted max / mean pooling: lane owns features 2l, 2l+1 ----
    const float* fb = g_feats + (size_t)b * V_ * FIN + 2 * lane;
    float mx0 = -CUDART_INF_F, mx1 = -CUDART_INF_F, sm0 = 0.f, sm1 = 0.f;
    #pragma unroll 8
    for (int n = 0; n < K_; n++) {
        float2 iw = s_iw[w][n];
        int off = __float_as_int(iw.y);
        float2 f = *reinterpret_cast<const float2*>(fb + off);
        float v0 = f.x * iw.x, v1 = f.y * iw.x;
        mx0 = fmaxf(mx0, v0); mx1 = fmaxf(mx1, v1);
        sm0 += v0;            sm1 += v1;
    }
    const int grow = b * V_ + q;
    float* o = g_coll + (size_t)grow * (2 * P_);
    float2 omx; omx.x = mx0; omx.y = mx1;
    float2 osm; osm.x = sm0 * (1.f / (float)K_); osm.y = sm1 * (1.f / (float)K_);
    *reinterpret_cast<float2*>(o + 2 * lane)      = omx;
    *reinterpret_cast<float2*>(o + 64 + 2 * lane) = osm;
}

// ============================================================
// Kernel 3: out = tanh([x | collected] @ W_out + b_out)
// 128x128 tile, 8x8/thread, BK=16, double-buffered smem
// ============================================================
__device__ __forceinline__ const float* a_src_ptr(const float* __restrict__ x,
                                                  int row, int gk) {
    return (gk < FIN) ? (x + (size_t)row * FIN + gk)
                      : (g_coll + (size_t)row * 128 + (gk - FIN));
}

__global__ void __launch_bounds__(256, 2) k_out(
    const float* __restrict__ x,
    const float* __restrict__ Wout, const float* __restrict__ bout,
    float* __restrict__ out)
{
    __shared__ float As[2][16 * 132];
    __shared__ float Bs[2][16 * 128];

    const int tidx = threadIdx.x;
    const int tx = tidx & 15, ty = tidx >> 4;
    const int r0 = blockIdx.x * 128;

    const int rowA0 = tidx >> 2,          kqA0 = (tidx & 3) * 4;
    const int rowA1 = (tidx + 256) >> 2,  kqA1 = ((tidx + 256) & 3) * 4;
    const int krB0  = tidx >> 5,          nB0  = (tidx & 31) * 4;
    const int krB1  = (tidx + 256) >> 5,  nB1  = ((tidx + 256) & 31) * 4;

    float acc[8][8];
    #pragma unroll
    for (int i = 0; i < 8; i++)
        #pragma unroll
        for (int j = 0; j < 8; j++) acc[i][j] = 0.f;

    float4 va0 = *reinterpret_cast<const float4*>(a_src_ptr(x, r0 + rowA0, kqA0));
    float4 va1 = *reinterpret_cast<const float4*>(a_src_ptr(x, r0 + rowA1, kqA1));
    float4 vb0 = *reinterpret_cast<const float4*>(Wout + (size_t)krB0 * 128 + nB0);
    float4 vb1 = *reinterpret_cast<const float4*>(Wout + (size_t)krB1 * 128 + nB1);
    {
        As[0][(kqA0 + 0) * 132 + rowA0] = va0.x;
        As[0][(kqA0 + 1) * 132 + rowA0] = va0.y;
        As[0][(kqA0 + 2) * 132 + rowA0] = va0.z;
        As[0][(kqA0 + 3) * 132 + rowA0] = va0.w;
        As[0][(kqA1 + 0) * 132 + rowA1] = va1.x;
        As[0][(kqA1 + 1) * 132 + rowA1] = va1.y;
        As[0][(kqA1 + 2) * 132 + rowA1] = va1.z;
        As[0][(kqA1 + 3) * 132 + rowA1] = va1.w;
        *reinterpret_cast<float4*>(&Bs[0][krB0 * 128 + nB0]) = vb0;
        *reinterpret_cast<float4*>(&Bs[0][krB1 * 128 + nB1]) = vb1;
    }
    __syncthreads();

    #pragma unroll
    for (int kt = 0; kt < 12; kt++) {
        const int cur = kt & 1;
        if (kt < 11) {
            int g0 = (kt + 1) * 16;
            va0 = *reinterpret_cast<const float4*>(a_src_ptr(x, r0 + rowA0, g0 + kqA0));
            va1 = *reinterpret_cast<const float4*>(a_src_ptr(x, r0 + rowA1, g0 + kqA1));
            vb0 = *reinterpret_cast<const float4*>(Wout + (size_t)(g0 + krB0) * 128 + nB0);
            vb1 = *reinterpret_cast<const float4*>(Wout + (size_t)(g0 + krB1) * 128 + nB1);
        }

        const float* Ac = As[cur];
        const float* Bc = Bs[cur];
        #pragma unroll
        for (int k = 0; k < 16; k++) {
            float a[8], bb[8];
            *reinterpret_cast<float4*>(&a[0]) =
                *reinterpret_cast<const float4*>(&Ac[k * 132 + ty * 8]);
            *reinterpret_cast<float4*>(&a[4]) =
                *reinterpret_cast<const float4*>(&Ac[k * 132 + ty * 8 + 4]);
            *reinterpret_cast<float4*>(&bb[0]) =
                *reinterpret_cast<const float4*>(&Bc[k * 128 + tx * 8]);
            *reinterpret_cast<float4*>(&bb[4]) =
                *reinterpret_cast<const float4*>(&Bc[k * 128 + tx * 8 + 4]);
            #pragma unroll
            for (int i = 0; i < 8; i++)
                #pragma unroll
                for (int j = 0; j < 8; j++)
                    acc[i][j] = fmaf(a[i], bb[j], acc[i][j]);
        }

        if (kt < 11) {
            const int nxt = cur ^ 1;
            As[nxt][(kqA0 + 0) * 132 + rowA0] = va0.x;
            As[nxt][(kqA0 + 1) * 132 + rowA0] = va0.y;
            As[nxt][(kqA0 + 2) * 132 + rowA0] = va0.z;
            As[nxt][(kqA0 + 3) * 132 + rowA0] = va0.w;
            As[nxt][(kqA1 + 0) * 132 + rowA1] = va1.x;
            As[nxt][(kqA1 + 1) * 132 + rowA1] = va1.y;
            As[nxt][(kqA1 + 2) * 132 + rowA1] = va1.z;
            As[nxt][(kqA1 + 3) * 132 + rowA1] = va1.w;
            *reinterpret_cast<float4*>(&Bs[nxt][krB0 * 128 + nB0]) = vb0;
            *reinterpret_cast<float4*>(&Bs[nxt][krB1 * 128 + nB1]) = vb1;
            __syncthreads();
        }
    }

    float bias[8];
    *reinterpret_cast<float4*>(&bias[0]) = *reinterpret_cast<const float4*>(&bout[tx * 8]);
    *reinterpret_cast<float4*>(&bias[4]) = *reinterpret_cast<const float4*>(&bout[tx * 8 + 4]);

    #pragma unroll
    for (int i = 0; i < 8; i++) {
        int row = r0 + ty * 8 + i;
        float4 o0, o1;
        o0.x = tanhf(acc[i][0] + bias[0]);
        o0.y = tanhf(acc[i][1] + bias[1]);
        o0.z = tanhf(acc[i][2] + bias[2]);
        o0.w = tanhf(acc[i][3] + bias[3]);
        o1.x = tanhf(acc[i][4] + bias[4]);
        o1.y = tanhf(acc[i][5] + bias[5]);
        o1.z = tanhf(acc[i][6] + bias[6]);
        o1.w = tanhf(acc[i][7] + bias[7]);
        *reinterpret_cast<float4*>(&out[(size_t)row * 128 + tx * 8])     = o0;
        *reinterpret_cast<float4*>(&out[(size_t)row * 128 + tx * 8 + 4]) = o1;
    }
}

// ============================================================
extern "C" void kernel_launch(void* const* d_in, const int* in_sizes, int n_in,
                              void* d_out, int out_size)
{
    const float* x    = (const float*)d_in[0];
    const float* Ws   = (const float*)d_in[2];
    const float* bs   = (const float*)d_in[3];
    const float* Wf   = (const float*)d_in[4];
    const float* bf   = (const float*)d_in[5];
    const float* Wout = (const float*)d_in[6];
    const float* bout = (const float*)d_in[7];
    float* out = (float*)d_out;

    k_transform<<<N_ / 64, 256>>>(x, Ws, bs, Wf, bf);
    k_knn<<<dim3(V_ / QPB, B_), 256>>>();
    k_out<<<N_ / 128, 256>>>(x, Wout, bout, out);
}